// round 1
// baseline (speedup 1.0000x reference)
#include <cuda_runtime.h>
#include <cuda_bf16.h>
#include <math.h>

// Problem shape (fixed by the dataset)
#define MAXN 100000
#define MAXE 1600000
#define F 128

// ---------------- device scratch (no allocations allowed) ----------------
__device__ int    d_cnt[MAXN + 1];
__device__ int    d_rowptr[MAXN + 1];
__device__ int    d_rowpos[MAXN];
__device__ int    d_esrc[MAXE];
__device__ float4 d_agg[MAXN * 32];   // [N][128] as float4[N][32]
__device__ float4 d_h[MAXN * 32];     // layer-1 output (relu'd)
__device__ float4 d_agg2[MAXN * 32];

// ---------------- CSR build ----------------
__global__ void count_kernel(const int* __restrict__ dst, int E) {
    int e = blockIdx.x * blockDim.x + threadIdx.x;
    if (e < E) atomicAdd(&d_cnt[dst[e]], 1);
}

// single-block exclusive scan over d_cnt[0..n) -> d_rowptr / d_rowpos, rowptr[n]=E
__global__ void scan_kernel(int n, int E) {
    const int T = 1024;
    int tid = threadIdx.x;
    int per = (n + T - 1) / T;
    int s = tid * per; if (s > n) s = n;
    int e = s + per;   if (e > n) e = n;
    int sum = 0;
    for (int i = s; i < e; i++) sum += d_cnt[i];

    __shared__ int wsum[32];
    int lane = tid & 31, wid = tid >> 5;
    int v = sum;
    #pragma unroll
    for (int o = 1; o < 32; o <<= 1) {
        int t = __shfl_up_sync(0xffffffffu, v, o);
        if (lane >= o) v += t;
    }
    if (lane == 31) wsum[wid] = v;
    __syncthreads();
    if (wid == 0) {
        int w = wsum[lane];
        #pragma unroll
        for (int o = 1; o < 32; o <<= 1) {
            int t = __shfl_up_sync(0xffffffffu, w, o);
            if (lane >= o) w += t;
        }
        wsum[lane] = w;
    }
    __syncthreads();
    int excl = (v - sum) + (wid > 0 ? wsum[wid - 1] : 0);
    int run = excl;
    for (int i = s; i < e; i++) {
        d_rowptr[i] = run;
        d_rowpos[i] = run;
        run += d_cnt[i];
    }
    if (tid == 0) d_rowptr[n] = E;
}

__global__ void scatter_kernel(const int* __restrict__ src,
                               const int* __restrict__ dst, int E) {
    int e = blockIdx.x * blockDim.x + threadIdx.x;
    if (e < E) {
        int p = atomicAdd(&d_rowpos[dst[e]], 1);
        d_esrc[p] = src[e];
    }
}

// ---------------- mean aggregation: one warp per node ----------------
__global__ void aggregate_kernel(const float4* __restrict__ feat,
                                 float4* __restrict__ out, int N) {
    int gw = (blockIdx.x * blockDim.x + threadIdx.x) >> 5;
    if (gw >= N) return;
    int lane = threadIdx.x & 31;
    int beg = d_rowptr[gw], end = d_rowptr[gw + 1];
    float ax = 0.f, ay = 0.f, az = 0.f, aw = 0.f;
    for (int j = beg; j < end; j++) {
        int s = __ldg(&d_esrc[j]);
        float4 v = feat[(size_t)s * 32 + lane];
        ax += v.x; ay += v.y; az += v.z; aw += v.w;
    }
    float inv = (end > beg) ? 1.f / (float)(end - beg) : 0.f;
    out[(size_t)gw * 32 + lane] = make_float4(ax * inv, ay * inv, az * inv, aw * inv);
}

// ---------------- layer-1 fused GEMM: out = relu([x|agg] @ [Ws;Wn] + b) ----------
// M x 256 @ 256 x 128, BM=128 BN=128 BK=16, 256 threads, 8x8 microtile,
// inner loop uses packed fma.rn.f32x2 (2 FMAs per fma-pipe issue).
#define BM 128
#define BN 128
#define BK 16

__global__ __launch_bounds__(256) void gemm_l1(
    const float* __restrict__ A0, const float* __restrict__ A1,
    const float* __restrict__ W0, const float* __restrict__ W1,
    const float* __restrict__ bias, float* __restrict__ out, int M) {
    __shared__ float As[BK][BM];
    __shared__ float Bs[BK][BN];
    int tid = threadIdx.x;
    int block_row = blockIdx.x * BM;
    int tx = tid & 15;   // col group (8 cols each)
    int ty = tid >> 4;   // row group (8 rows each)

    unsigned long long acc[8][4];
    #pragma unroll
    for (int i = 0; i < 8; i++)
        #pragma unroll
        for (int j = 0; j < 4; j++) acc[i][j] = 0ull;

    for (int kk = 0; kk < 256; kk += BK) {
        const float* Ap = (kk < 128) ? A0 : A1;
        const float* Wp = (kk < 128) ? W0 : W1;
        int kbase = (kk < 128) ? kk : (kk - 128);

        // A tile: 128 rows x 16 cols (512 float4 loads)
        #pragma unroll
        for (int r = 0; r < 2; r++) {
            int idx = tid + r * 256;
            int row = idx >> 2, c4 = idx & 3;
            int grow = block_row + row;
            float4 v = make_float4(0.f, 0.f, 0.f, 0.f);
            if (grow < M)
                v = *(const float4*)(Ap + (size_t)grow * 128 + kbase + c4 * 4);
            As[c4 * 4 + 0][row] = v.x;
            As[c4 * 4 + 1][row] = v.y;
            As[c4 * 4 + 2][row] = v.z;
            As[c4 * 4 + 3][row] = v.w;
        }
        // B tile: 16 rows x 128 cols
        #pragma unroll
        for (int r = 0; r < 2; r++) {
            int idx = tid + r * 256;
            int row = idx >> 5, c4 = idx & 31;
            *(float4*)&Bs[row][c4 * 4] =
                *(const float4*)(Wp + (size_t)(kbase + row) * 128 + c4 * 4);
        }
        __syncthreads();

        #pragma unroll
        for (int k = 0; k < BK; k++) {
            float a[8];
            unsigned long long a2[8], b2[4];
            #pragma unroll
            for (int i = 0; i < 8; i++) a[i] = As[k][ty * 8 + i];
            #pragma unroll
            for (int i = 0; i < 8; i++)
                asm("mov.b64 %0, {%1, %1};" : "=l"(a2[i]) : "f"(a[i]));
            #pragma unroll
            for (int j = 0; j < 4; j++)
                b2[j] = *(const unsigned long long*)&Bs[k][tx * 8 + 2 * j];
            #pragma unroll
            for (int i = 0; i < 8; i++)
                #pragma unroll
                for (int j = 0; j < 4; j++)
                    asm("fma.rn.f32x2 %0, %1, %2, %0;"
                        : "+l"(acc[i][j]) : "l"(a2[i]), "l"(b2[j]));
        }
        __syncthreads();
    }

    // epilogue: bias + relu, float2 stores
    #pragma unroll
    for (int i = 0; i < 8; i++) {
        int grow = block_row + ty * 8 + i;
        if (grow >= M) continue;
        #pragma unroll
        for (int j = 0; j < 4; j++) {
            float lo, hi;
            asm("mov.b64 {%0, %1}, %2;" : "=f"(lo), "=f"(hi) : "l"(acc[i][j]));
            int n0 = tx * 8 + 2 * j;
            lo = fmaxf(lo + __ldg(&bias[n0]), 0.f);
            hi = fmaxf(hi + __ldg(&bias[n0 + 1]), 0.f);
            float2 st = make_float2(lo, hi);
            *(float2*)&out[(size_t)grow * 128 + n0] = st;
        }
    }
}

// ---------------- layer 2 + log_softmax: one warp per node ----------------
__global__ void layer2_kernel(const float4* __restrict__ h,
                              const float4* __restrict__ agg2,
                              const float* __restrict__ Ws,
                              const float* __restrict__ Wn,
                              const float* __restrict__ b,
                              float* __restrict__ out, int N) {
    __shared__ float sWs[256], sWn[256];
    int tid = threadIdx.x;
    sWs[tid] = Ws[tid];
    sWn[tid] = Wn[tid];
    __syncthreads();

    int gw = (blockIdx.x * blockDim.x + tid) >> 5;
    if (gw >= N) return;
    int lane = tid & 31;

    float4 hv = h[(size_t)gw * 32 + lane];
    float4 av = agg2[(size_t)gw * 32 + lane];
    float z0 = 0.f, z1 = 0.f;
    int k0 = lane * 4;
    float hx[4] = {hv.x, hv.y, hv.z, hv.w};
    float ax[4] = {av.x, av.y, av.z, av.w};
    #pragma unroll
    for (int i = 0; i < 4; i++) {
        int k = k0 + i;
        z0 += hx[i] * sWs[k * 2 + 0] + ax[i] * sWn[k * 2 + 0];
        z1 += hx[i] * sWs[k * 2 + 1] + ax[i] * sWn[k * 2 + 1];
    }
    #pragma unroll
    for (int o = 16; o > 0; o >>= 1) {
        z0 += __shfl_down_sync(0xffffffffu, z0, o);
        z1 += __shfl_down_sync(0xffffffffu, z1, o);
    }
    if (lane == 0) {
        z0 += b[0];
        z1 += b[1];
        float m = fmaxf(z0, z1);
        float lse = m + log1pf(expf(fminf(z0, z1) - m));
        out[(size_t)gw * 2 + 0] = z0 - lse;
        out[(size_t)gw * 2 + 1] = z1 - lse;
    }
}

// ---------------- launch ----------------
extern "C" void kernel_launch(void* const* d_in, const int* in_sizes, int n_in,
                              void* d_out, int out_size) {
    const float* x   = (const float*)d_in[0];
    const int*   src = (const int*)d_in[1];
    const int*   dst = (const int*)d_in[2];
    const float* ws1 = (const float*)d_in[3];
    const float* wn1 = (const float*)d_in[4];
    const float* b1  = (const float*)d_in[5];
    const float* ws2 = (const float*)d_in[6];
    const float* wn2 = (const float*)d_in[7];
    const float* b2  = (const float*)d_in[8];
    float* out = (float*)d_out;

    int N = in_sizes[0] / F;
    int E = in_sizes[1];
    if (N > MAXN) N = MAXN;
    if (E > MAXE) E = MAXE;

    void *p_cnt, *p_agg, *p_h, *p_agg2;
    cudaGetSymbolAddress(&p_cnt, d_cnt);
    cudaGetSymbolAddress(&p_agg, d_agg);
    cudaGetSymbolAddress(&p_h, d_h);
    cudaGetSymbolAddress(&p_agg2, d_agg2);
    float4* agg  = (float4*)p_agg;
    float4* h    = (float4*)p_h;
    float4* agg2 = (float4*)p_agg2;

    cudaMemsetAsync(p_cnt, 0, (size_t)N * sizeof(int));

    int eb = (E + 255) / 256;
    count_kernel<<<eb, 256>>>(dst, E);
    scan_kernel<<<1, 1024>>>(N, E);
    scatter_kernel<<<eb, 256>>>(src, dst, E);

    int aggBlocks = (N * 32 + 255) / 256;  // one warp per node
    aggregate_kernel<<<aggBlocks, 256>>>((const float4*)x, agg, N);

    gemm_l1<<<(N + BM - 1) / BM, 256>>>(x, (const float*)agg, ws1, wn1, b1,
                                        (float*)h, N);

    aggregate_kernel<<<aggBlocks, 256>>>((const float4*)h, agg2, N);

    layer2_kernel<<<aggBlocks, 256>>>((const float4*)h, (const float4*)agg2,
                                      ws2, wn2, b2, out, N);
}

// round 2
// speedup vs baseline: 1.1826x; 1.1826x over previous
#include <cuda_runtime.h>
#include <math.h>

// Problem shape (fixed by the dataset)
#define MAXN 100000
#define MAXE 1600000

// ---------------- device scratch (no allocations allowed) ----------------
__device__ int    d_cnt[MAXN + 1];
__device__ int    d_rowptr[MAXN + 1];
__device__ int    d_rowpos[MAXN];
__device__ int    d_esrc[MAXE];
__device__ float4 d_agg[MAXN * 32];   // [N][128] as float4[N][32]
__device__ float2 d_s[MAXN];          // h @ Ws2   (per node, 2 logits)
__device__ float2 d_t[MAXN];          // h @ Wn2   (per node, 2 logits)

// ---------------- CSR build ----------------
__global__ void zero_kernel(int n) {
    int i = blockIdx.x * blockDim.x + threadIdx.x;
    if (i < n) d_cnt[i] = 0;
}

__global__ void count_kernel(const int* __restrict__ dst, int E) {
    int e = blockIdx.x * blockDim.x + threadIdx.x;
    if (e < E) atomicAdd(&d_cnt[dst[e]], 1);
}

// single-block exclusive scan over d_cnt[0..n) -> d_rowptr / d_rowpos
__global__ void scan_kernel(int n, int E) {
    const int T = 1024;
    int tid = threadIdx.x;
    int per = (n + T - 1) / T;
    int s = tid * per; if (s > n) s = n;
    int e = s + per;   if (e > n) e = n;
    int sum = 0;
    for (int i = s; i < e; i++) sum += d_cnt[i];

    __shared__ int wsum[32];
    int lane = tid & 31, wid = tid >> 5;
    int v = sum;
    #pragma unroll
    for (int o = 1; o < 32; o <<= 1) {
        int t = __shfl_up_sync(0xffffffffu, v, o);
        if (lane >= o) v += t;
    }
    if (lane == 31) wsum[wid] = v;
    __syncthreads();
    if (wid == 0) {
        int w = wsum[lane];
        #pragma unroll
        for (int o = 1; o < 32; o <<= 1) {
            int t = __shfl_up_sync(0xffffffffu, w, o);
            if (lane >= o) w += t;
        }
        wsum[lane] = w;
    }
    __syncthreads();
    int excl = (v - sum) + (wid > 0 ? wsum[wid - 1] : 0);
    int run = excl;
    for (int i = s; i < e; i++) {
        d_rowptr[i] = run;
        d_rowpos[i] = run;
        run += d_cnt[i];
    }
    if (tid == 0) d_rowptr[n] = E;
}

__global__ void scatter_kernel(const int* __restrict__ src,
                               const int* __restrict__ dst, int E) {
    int e = blockIdx.x * blockDim.x + threadIdx.x;
    if (e < E) {
        int p = atomicAdd(&d_rowpos[dst[e]], 1);
        d_esrc[p] = src[e];
    }
}

// ---------------- mean aggregation (128-dim): one warp per node ----------------
__global__ void aggregate_kernel(const float4* __restrict__ feat,
                                 float4* __restrict__ out, int N) {
    int gw = (blockIdx.x * blockDim.x + threadIdx.x) >> 5;
    if (gw >= N) return;
    int lane = threadIdx.x & 31;
    int beg = d_rowptr[gw], end = d_rowptr[gw + 1];
    float ax = 0.f, ay = 0.f, az = 0.f, aw = 0.f;
    for (int j = beg; j < end; j++) {
        int s = __ldg(&d_esrc[j]);
        float4 v = feat[(size_t)s * 32 + lane];
        ax += v.x; ay += v.y; az += v.z; aw += v.w;
    }
    float inv = (end > beg) ? 1.f / (float)(end - beg) : 0.f;
    out[(size_t)gw * 32 + lane] = make_float4(ax * inv, ay * inv, az * inv, aw * inv);
}

// ---------------- layer-1 GEMM fused with layer-2 projections ----------------
// h_row = relu([x_row | agg_row] @ [Ws1; Wn1] + b1)   (never stored)
// s_row = h_row @ Ws2, t_row = h_row @ Wn2            (stored, 2+2 floats)
// cp.async double-buffered, packed fma.rn.f32x2 inner loop.
#define BM 128
#define BK 16
#define AP 20  // padded row stride of As (floats); keeps cp.async dst 16B-aligned

__device__ __forceinline__ unsigned smem_u32(const void* p) {
    return (unsigned)__cvta_generic_to_shared(p);
}

__global__ __launch_bounds__(256, 2) void gemm_l1(
    const float* __restrict__ x, const float* __restrict__ agg,
    const float* __restrict__ Ws1, const float* __restrict__ Wn1,
    const float* __restrict__ b1,
    const float* __restrict__ Ws2, const float* __restrict__ Wn2,
    float2* __restrict__ s_out, float2* __restrict__ t_out, int M)
{
    __shared__ float As[2][BM][AP];
    __shared__ float Bs[2][BK][128];
    __shared__ float sW2[512];   // [c][4]: Ws2[c][0..1], Wn2[c][0..1]
    __shared__ float sB1[128];

    int tid = threadIdx.x;
    int tx = tid & 15, ty = tid >> 4;
    int block_row = blockIdx.x * BM;

    auto load_stage = [&](int st, int kk) {
        const float* Ap = (kk < 8) ? x : agg;
        const float* Wp = (kk < 8) ? Ws1 : Wn1;
        int kbase = (kk & 7) * BK;
        #pragma unroll
        for (int r = 0; r < 2; r++) {
            int c = tid + r * 256;              // 0..511
            int row = c >> 2, kc = c & 3;
            int ar = block_row + row; if (ar >= M) ar = M - 1;
            unsigned dst = smem_u32(&As[st][row][kc * 4]);
            const float* src = Ap + (size_t)ar * 128 + kbase + kc * 4;
            asm volatile("cp.async.cg.shared.global [%0], [%1], 16;"
                         :: "r"(dst), "l"(src));
        }
        #pragma unroll
        for (int r = 0; r < 2; r++) {
            int c = tid + r * 256;
            int row = c >> 5, col = (c & 31) * 4;
            unsigned dst = smem_u32(&Bs[st][row][col]);
            const float* src = Wp + (size_t)(kbase + row) * 128 + col;
            asm volatile("cp.async.cg.shared.global [%0], [%1], 16;"
                         :: "r"(dst), "l"(src));
        }
        asm volatile("cp.async.commit_group;");
    };

    load_stage(0, 0);
    load_stage(1, 1);

    // epilogue constants, loaded while cp.async is in flight
    if (tid < 128) sB1[tid] = b1[tid];
    #pragma unroll
    for (int r = 0; r < 2; r++) {
        int idx = tid + r * 256;
        int c = idx >> 2, q = idx & 3;
        sW2[idx] = (q < 2) ? Ws2[c * 2 + q] : Wn2[c * 2 + (q - 2)];
    }

    unsigned long long acc[8][4];
    #pragma unroll
    for (int i = 0; i < 8; i++)
        #pragma unroll
        for (int j = 0; j < 4; j++) acc[i][j] = 0ull;

    asm volatile("cp.async.wait_group 1;" ::: "memory");
    __syncthreads();

    for (int kk = 0; kk < 16; kk++) {
        int st = kk & 1;
        #pragma unroll
        for (int k = 0; k < BK; k++) {
            unsigned long long a2[8], b2[4];
            #pragma unroll
            for (int i = 0; i < 8; i++) {
                float av = As[st][ty * 8 + i][k];
                asm("mov.b64 %0, {%1, %1};" : "=l"(a2[i]) : "f"(av));
            }
            ulonglong2 bb0 = *(const ulonglong2*)&Bs[st][k][tx * 8];
            ulonglong2 bb1 = *(const ulonglong2*)&Bs[st][k][tx * 8 + 4];
            b2[0] = bb0.x; b2[1] = bb0.y; b2[2] = bb1.x; b2[3] = bb1.y;
            #pragma unroll
            for (int i = 0; i < 8; i++)
                #pragma unroll
                for (int j = 0; j < 4; j++)
                    asm("fma.rn.f32x2 %0, %1, %2, %0;"
                        : "+l"(acc[i][j]) : "l"(a2[i]), "l"(b2[j]));
        }
        __syncthreads();
        if (kk + 2 < 16) load_stage(st, kk + 2);
        else asm volatile("cp.async.commit_group;");
        if (kk + 1 < 16) {
            asm volatile("cp.async.wait_group 1;" ::: "memory");
            __syncthreads();
        }
    }

    // epilogue: bias + relu -> project to 4 values (s0,s1,t0,t1), half-warp reduce
    #pragma unroll
    for (int i = 0; i < 8; i++) {
        int grow = block_row + ty * 8 + i;
        float z0 = 0.f, z1 = 0.f, z2 = 0.f, z3 = 0.f;
        #pragma unroll
        for (int j = 0; j < 4; j++) {
            float lo, hi;
            asm("mov.b64 {%0, %1}, %2;" : "=f"(lo), "=f"(hi) : "l"(acc[i][j]));
            int c0 = tx * 8 + 2 * j;
            lo = fmaxf(lo + sB1[c0], 0.f);
            hi = fmaxf(hi + sB1[c0 + 1], 0.f);
            z0 += lo * sW2[c0 * 4 + 0] + hi * sW2[(c0 + 1) * 4 + 0];
            z1 += lo * sW2[c0 * 4 + 1] + hi * sW2[(c0 + 1) * 4 + 1];
            z2 += lo * sW2[c0 * 4 + 2] + hi * sW2[(c0 + 1) * 4 + 2];
            z3 += lo * sW2[c0 * 4 + 3] + hi * sW2[(c0 + 1) * 4 + 3];
        }
        #pragma unroll
        for (int o = 1; o < 16; o <<= 1) {
            z0 += __shfl_xor_sync(0xffffffffu, z0, o);
            z1 += __shfl_xor_sync(0xffffffffu, z1, o);
            z2 += __shfl_xor_sync(0xffffffffu, z2, o);
            z3 += __shfl_xor_sync(0xffffffffu, z3, o);
        }
        if (tx == 0 && grow < M) {
            s_out[grow] = make_float2(z0, z1);
            t_out[grow] = make_float2(z2, z3);
        }
    }
}

// ---------------- finalize: mean(t) over neighbors + s + b2 -> log_softmax ----
__global__ void finalize_kernel(const float* __restrict__ b2,
                                float* __restrict__ out, int N) {
    int v = blockIdx.x * blockDim.x + threadIdx.x;
    if (v >= N) return;
    int beg = d_rowptr[v], end = d_rowptr[v + 1];
    float t0 = 0.f, t1 = 0.f;
    for (int j = beg; j < end; j++) {
        float2 tv = d_t[__ldg(&d_esrc[j])];
        t0 += tv.x; t1 += tv.y;
    }
    float inv = (end > beg) ? 1.f / (float)(end - beg) : 0.f;
    float2 s = d_s[v];
    float z0 = s.x + b2[0] + t0 * inv;
    float z1 = s.y + b2[1] + t1 * inv;
    float m = fmaxf(z0, z1);
    float lse = m + log1pf(expf(fminf(z0, z1) - m));
    out[2 * v]     = z0 - lse;
    out[2 * v + 1] = z1 - lse;
}

// ---------------- launch ----------------
extern "C" void kernel_launch(void* const* d_in, const int* in_sizes, int n_in,
                              void* d_out, int out_size) {
    const float* x   = (const float*)d_in[0];
    const int*   src = (const int*)d_in[1];
    const int*   dst = (const int*)d_in[2];
    const float* ws1 = (const float*)d_in[3];
    const float* wn1 = (const float*)d_in[4];
    const float* b1  = (const float*)d_in[5];
    const float* ws2 = (const float*)d_in[6];
    const float* wn2 = (const float*)d_in[7];
    const float* b2  = (const float*)d_in[8];
    float* out = (float*)d_out;

    int N = in_sizes[0] / 128;
    int E = in_sizes[1];
    if (N > MAXN) N = MAXN;
    if (E > MAXE) E = MAXE;

    void *p_agg, *p_s, *p_t;
    cudaGetSymbolAddress(&p_agg, d_agg);
    cudaGetSymbolAddress(&p_s, d_s);
    cudaGetSymbolAddress(&p_t, d_t);

    int eb = (E + 255) / 256;
    int nb = (N + 255) / 256;

    zero_kernel<<<(N + 256) / 256, 256>>>(N + 1);          // launch 1
    count_kernel<<<eb, 256>>>(dst, E);                     // launch 2
    scan_kernel<<<1, 1024>>>(N, E);                        // launch 3
    scatter_kernel<<<eb, 256>>>(src, dst, E);              // launch 4

    int aggBlocks = (N * 32 + 255) / 256;
    aggregate_kernel<<<aggBlocks, 256>>>((const float4*)x, // launch 5
                                         (float4*)p_agg, N);

    gemm_l1<<<(N + BM - 1) / BM, 256>>>(                   // launch 6 (ncu slot)
        x, (const float*)p_agg, ws1, wn1, b1, ws2, wn2,
        (float2*)p_s, (float2*)p_t, N);

    finalize_kernel<<<nb, 256>>>(b2, out, N);              // launch 7
}

// round 5
// speedup vs baseline: 1.5803x; 1.3363x over previous
#include <cuda_runtime.h>
#include <math.h>

#define MAXN 100000
#define MAXE 1600000

// ---------------- device scratch ----------------
__device__ int    d_cnt[MAXN + 1];
__device__ int    d_rowptr[MAXN + 1];
__device__ int    d_rowpos[MAXN];
__device__ int    d_esrc[MAXE];
__device__ float4 d_agg[MAXN * 32];      // [N][128]
__device__ float2 d_s[MAXN];             // h @ Ws2
__device__ float2 d_t[MAXN];             // h @ Wn2
__device__ float  d_Bimg[256 * 136];     // padded tf32 image of [Ws1;Wn1] (K x N, stride 136)

// ---------------- zero + weight-image prep (one kernel, launch 1) ----------
// d_Bimg[k][n] = tf32(W[k][n]), rows padded to 136 floats for bank-conflict-free LDS.
__global__ void zero_prep_kernel(int n, const float* __restrict__ Ws1,
                                 const float* __restrict__ Wn1) {
    int i = blockIdx.x * blockDim.x + threadIdx.x;
    if (i < n) d_cnt[i] = 0;
    if (i < 256 * 136) {
        int k = i / 136, c = i - k * 136;
        unsigned bits = 0;
        if (c < 128) {
            const float* W = (k < 128) ? Ws1 : Wn1;
            float v = W[(k & 127) * 128 + c];
            asm("cvt.rn.tf32.f32 %0, %1;" : "=r"(bits) : "f"(v));
        }
        ((unsigned*)d_Bimg)[i] = bits;
    }
}

// ---------------- CSR build ----------------
__global__ void count_kernel(const int* __restrict__ dst, int E) {
    int e = blockIdx.x * blockDim.x + threadIdx.x;
    if (e < E) atomicAdd(&d_cnt[dst[e]], 1);
}

__global__ void scan_kernel(int n, int E) {
    const int T = 1024;
    int tid = threadIdx.x;
    int per = (n + T - 1) / T;
    int s = tid * per; if (s > n) s = n;
    int e = s + per;   if (e > n) e = n;
    int sum = 0;
    for (int i = s; i < e; i++) sum += d_cnt[i];

    __shared__ int wsum[32];
    int lane = tid & 31, wid = tid >> 5;
    int v = sum;
    #pragma unroll
    for (int o = 1; o < 32; o <<= 1) {
        int t = __shfl_up_sync(0xffffffffu, v, o);
        if (lane >= o) v += t;
    }
    if (lane == 31) wsum[wid] = v;
    __syncthreads();
    if (wid == 0) {
        int w = wsum[lane];
        #pragma unroll
        for (int o = 1; o < 32; o <<= 1) {
            int t = __shfl_up_sync(0xffffffffu, w, o);
            if (lane >= o) w += t;
        }
        wsum[lane] = w;
    }
    __syncthreads();
    int excl = (v - sum) + (wid > 0 ? wsum[wid - 1] : 0);
    int run = excl;
    for (int i = s; i < e; i++) {
        d_rowptr[i] = run;
        d_rowpos[i] = run;
        run += d_cnt[i];
    }
    if (tid == 0) d_rowptr[n] = E;
}

__global__ void scatter_kernel(const int* __restrict__ src,
                               const int* __restrict__ dst, int E) {
    int e = blockIdx.x * blockDim.x + threadIdx.x;
    if (e < E) {
        int p = atomicAdd(&d_rowpos[dst[e]], 1);
        d_esrc[p] = src[e];
    }
}

// ---------------- mean aggregation (128-dim): one warp per node ------------
__global__ void aggregate_kernel(const float4* __restrict__ feat,
                                 float4* __restrict__ out, int N) {
    int gw = (blockIdx.x * blockDim.x + threadIdx.x) >> 5;
    if (gw >= N) return;
    int lane = threadIdx.x & 31;
    int beg = d_rowptr[gw], end = d_rowptr[gw + 1];
    float ax = 0.f, ay = 0.f, az = 0.f, aw = 0.f;
    for (int j = beg; j < end; j++) {
        int s = __ldg(&d_esrc[j]);
        float4 v = feat[(size_t)s * 32 + lane];
        ax += v.x; ay += v.y; az += v.z; aw += v.w;
    }
    float inv = (end > beg) ? 1.f / (float)(end - beg) : 0.f;
    out[(size_t)gw * 32 + lane] = make_float4(ax * inv, ay * inv, az * inv, aw * inv);
}

// ---------------- mma.sync tf32 GEMM + fused layer-2 epilogue --------------
// D[128,128] = [x|agg](128x256) @ [Ws1;Wn1](256x128), fp32 accum.
// 256 thr = 8 warps in 4(m) x 2(n); warp tile 32x64; m16n8k8 tf32 mma.
// Epilogue: h = relu(D+b1); s = h@Ws2, t = h@Wn2 (4 floats/row).
#define A_STRIDE 36           // floats; bank = (4r+k)%32 all-distinct
#define B_STRIDE 136          // floats; bank = (8k+n)%32 all-distinct
#define A_STAGE  (128 * A_STRIDE)
#define SM_B1    0
#define SM_W2    512
#define SM_A     4096
#define SM_B     (SM_A + 2 * A_STAGE * 4)        // 40960
#define SM_ZB    SM_A                            // reuse A area for reduction
#define SM_TOTAL (SM_B + 256 * B_STRIDE * 4)     // 180224

__device__ __forceinline__ unsigned smem_u32(const void* p) {
    return (unsigned)__cvta_generic_to_shared(p);
}
__device__ __forceinline__ unsigned f2tf32(float v) {
    unsigned r;
    asm("cvt.rn.tf32.f32 %0, %1;" : "=r"(r) : "f"(v));
    return r;
}

__global__ __launch_bounds__(256, 1) void gemm_l1(
    const float* __restrict__ x, const float* __restrict__ agg,
    const float* __restrict__ b1,
    const float* __restrict__ Ws2, const float* __restrict__ Wn2,
    float2* __restrict__ s_out, float2* __restrict__ t_out, int M)
{
    extern __shared__ char smem[];
    unsigned sbase = smem_u32(smem);
    float* As  = (float*)(smem + SM_A);
    float* Bs  = (float*)(smem + SM_B);
    float* sB1 = (float*)(smem + SM_B1);
    float* sW2 = (float*)(smem + SM_W2);
    float* zbuf = (float*)(smem + SM_ZB);   // [2][128][4]

    int tid  = threadIdx.x;
    int wid  = tid >> 5;
    int lane = tid & 31;
    int g    = lane >> 2;      // group id 0..7
    int tg   = lane & 3;       // thread-in-group
    int mw   = wid & 3;        // warp m index
    int nw   = wid >> 2;       // warp n index
    int mbase = mw * 32;
    int nbase = nw * 64;
    int block_row = blockIdx.x * 128;

    // B fill: 8704 x 16B linear cp.async from the padded gmem image
    {
        const char* bsrc = (const char*)d_Bimg;
        #pragma unroll
        for (int t = 0; t < 34; t++) {
            int idx = tid + t * 256;
            asm volatile("cp.async.cg.shared.global [%0], [%1], 16;"
                         :: "r"(sbase + SM_B + idx * 16), "l"(bsrc + idx * 16));
        }
    }

    auto load_A = [&](int st, int c) {
        const float* Ap = (c < 4) ? x : agg;
        int kbase = (c & 3) * 32;
        #pragma unroll
        for (int t = 0; t < 4; t++) {
            int idx = tid + t * 256;
            int row = idx >> 3, kc = idx & 7;
            int ar = block_row + row; if (ar >= M) ar = M - 1;
            unsigned dst = sbase + SM_A + (st * A_STAGE + row * A_STRIDE + kc * 4) * 4;
            const float* srcp = Ap + (size_t)ar * 128 + kbase + kc * 4;
            asm volatile("cp.async.cg.shared.global [%0], [%1], 16;"
                         :: "r"(dst), "l"(srcp));
        }
        asm volatile("cp.async.commit_group;");
    };

    load_A(0, 0);   // group 0 = B + chunk0
    load_A(1, 1);   // group 1 = chunk1

    // epilogue constants
    if (tid < 128) sB1[tid] = b1[tid];
    #pragma unroll
    for (int r = 0; r < 2; r++) {
        int idx = tid + r * 256;
        int c = idx >> 2, q = idx & 3;
        sW2[idx] = (q < 2) ? Ws2[c * 2 + q] : Wn2[c * 2 + (q - 2)];
    }

    float acc[2][8][4];
    #pragma unroll
    for (int i = 0; i < 2; i++)
        #pragma unroll
        for (int j = 0; j < 8; j++)
            #pragma unroll
            for (int q = 0; q < 4; q++) acc[i][j][q] = 0.f;

    for (int c = 0; c < 8; c++) {
        int st = c & 1;
        if (c < 7) asm volatile("cp.async.wait_group 1;" ::: "memory");
        else       asm volatile("cp.async.wait_group 0;" ::: "memory");
        __syncthreads();

        const float* as = As + st * A_STAGE;
        #pragma unroll
        for (int ks = 0; ks < 4; ks++) {
            int kk = ks * 8;
            unsigned a[2][4];
            #pragma unroll
            for (int i = 0; i < 2; i++) {
                int r0 = (mbase + i * 16 + g) * A_STRIDE;
                int r1 = r0 + 8 * A_STRIDE;
                a[i][0] = f2tf32(as[r0 + kk + tg]);
                a[i][1] = f2tf32(as[r1 + kk + tg]);
                a[i][2] = f2tf32(as[r0 + kk + tg + 4]);
                a[i][3] = f2tf32(as[r1 + kk + tg + 4]);
            }
            int kb = (c * 32 + kk + tg) * B_STRIDE;
            #pragma unroll
            for (int j = 0; j < 8; j++) {
                int col = nbase + j * 8 + g;
                unsigned b0 = __float_as_uint(Bs[kb + col]);
                unsigned b1v = __float_as_uint(Bs[kb + 4 * B_STRIDE + col]);
                #pragma unroll
                for (int i = 0; i < 2; i++) {
                    asm volatile(
                        "mma.sync.aligned.m16n8k8.row.col.f32.tf32.tf32.f32 "
                        "{%0,%1,%2,%3}, {%4,%5,%6,%7}, {%8,%9}, {%0,%1,%2,%3};"
                        : "+f"(acc[i][j][0]), "+f"(acc[i][j][1]),
                          "+f"(acc[i][j][2]), "+f"(acc[i][j][3])
                        : "r"(a[i][0]), "r"(a[i][1]), "r"(a[i][2]), "r"(a[i][3]),
                          "r"(b0), "r"(b1v));
                }
            }
        }
        __syncthreads();               // all warps done reading stage st
        if (c + 2 < 8) load_A(st, c + 2);
    }

    // ---- epilogue: bias+relu, project to 4 vals per row, reduce ----
    float z[2][2][4];   // [m-tile][half(row g / g+8)][q]
    #pragma unroll
    for (int i = 0; i < 2; i++)
        #pragma unroll
        for (int h = 0; h < 2; h++)
            #pragma unroll
            for (int q = 0; q < 4; q++) z[i][h][q] = 0.f;

    #pragma unroll
    for (int j = 0; j < 8; j++) {
        int col0 = nbase + j * 8 + 2 * tg;
        float bb0 = sB1[col0], bb1 = sB1[col0 + 1];
        float4 w0 = *(const float4*)&sW2[col0 * 4];
        float4 w1 = *(const float4*)&sW2[(col0 + 1) * 4];
        #pragma unroll
        for (int i = 0; i < 2; i++) {
            #pragma unroll
            for (int h = 0; h < 2; h++) {
                float h0 = fmaxf(acc[i][j][2 * h]     + bb0, 0.f);
                float h1 = fmaxf(acc[i][j][2 * h + 1] + bb1, 0.f);
                z[i][h][0] += h0 * w0.x + h1 * w1.x;
                z[i][h][1] += h0 * w0.y + h1 * w1.y;
                z[i][h][2] += h0 * w0.z + h1 * w1.z;
                z[i][h][3] += h0 * w0.w + h1 * w1.w;
            }
        }
    }
    // reduce over tg (lanes within quad)
    #pragma unroll
    for (int i = 0; i < 2; i++)
        #pragma unroll
        for (int h = 0; h < 2; h++)
            #pragma unroll
            for (int q = 0; q < 4; q++) {
                z[i][h][q] += __shfl_xor_sync(0xffffffffu, z[i][h][q], 1);
                z[i][h][q] += __shfl_xor_sync(0xffffffffu, z[i][h][q], 2);
            }

    __syncthreads();    // safe to overwrite As area with zbuf
    if (tg == 0) {
        #pragma unroll
        for (int i = 0; i < 2; i++)
            #pragma unroll
            for (int h = 0; h < 2; h++) {
                int row = mbase + i * 16 + h * 8 + g;
                float4 v = make_float4(z[i][h][0], z[i][h][1], z[i][h][2], z[i][h][3]);
                *(float4*)&zbuf[(nw * 128 + row) * 4] = v;
            }
    }
    __syncthreads();
    if (tid < 128) {
        float4 v0 = *(const float4*)&zbuf[tid * 4];
        float4 v1 = *(const float4*)&zbuf[(128 + tid) * 4];
        int grow = block_row + tid;
        if (grow < M) {
            s_out[grow] = make_float2(v0.x + v1.x, v0.y + v1.y);
            t_out[grow] = make_float2(v0.z + v1.z, v0.w + v1.w);
        }
    }
}

// ---------------- finalize: mean(t) over neighbors + s + b2 -> log_softmax --
__global__ void finalize_kernel(const float* __restrict__ b2,
                                float* __restrict__ out, int N) {
    int v = blockIdx.x * blockDim.x + threadIdx.x;
    if (v >= N) return;
    int beg = d_rowptr[v], end = d_rowptr[v + 1];
    float t0 = 0.f, t1 = 0.f;
    for (int j = beg; j < end; j++) {
        float2 tv = d_t[__ldg(&d_esrc[j])];
        t0 += tv.x; t1 += tv.y;
    }
    float inv = (end > beg) ? 1.f / (float)(end - beg) : 0.f;
    float2 s = d_s[v];
    float z0 = s.x + b2[0] + t0 * inv;
    float z1 = s.y + b2[1] + t1 * inv;
    float m = fmaxf(z0, z1);
    float lse = m + log1pf(expf(fminf(z0, z1) - m));
    out[2 * v]     = z0 - lse;
    out[2 * v + 1] = z1 - lse;
}

// ---------------- launch ----------------
extern "C" void kernel_launch(void* const* d_in, const int* in_sizes, int n_in,
                              void* d_out, int out_size) {
    const float* x   = (const float*)d_in[0];
    const int*   src = (const int*)d_in[1];
    const int*   dst = (const int*)d_in[2];
    const float* ws1 = (const float*)d_in[3];
    const float* wn1 = (const float*)d_in[4];
    const float* b1  = (const float*)d_in[5];
    const float* ws2 = (const float*)d_in[6];
    const float* wn2 = (const float*)d_in[7];
    const float* b2  = (const float*)d_in[8];
    float* out = (float*)d_out;

    int N = in_sizes[0] / 128;
    int E = in_sizes[1];
    if (N > MAXN) N = MAXN;
    if (E > MAXE) E = MAXE;

    void *p_agg, *p_s, *p_t;
    cudaGetSymbolAddress(&p_agg, d_agg);
    cudaGetSymbolAddress(&p_s, d_s);
    cudaGetSymbolAddress(&p_t, d_t);

    static bool attr_set = false;
    if (!attr_set) {
        cudaFuncSetAttribute(gemm_l1, cudaFuncAttributeMaxDynamicSharedMemorySize,
                             SM_TOTAL);
        attr_set = true;
    }

    int eb = (E + 255) / 256;
    int nb = (N + 255) / 256;
    int zp = (((N + 1) > 256 * 136 ? (N + 1) : 256 * 136) + 255) / 256;

    zero_prep_kernel<<<zp, 256>>>(N + 1, ws1, wn1);        // launch 1
    count_kernel<<<eb, 256>>>(dst, E);                     // launch 2
    scan_kernel<<<1, 1024>>>(N, E);                        // launch 3
    scatter_kernel<<<eb, 256>>>(src, dst, E);              // launch 4

    int aggBlocks = (N * 32 + 255) / 256;
    aggregate_kernel<<<aggBlocks, 256>>>((const float4*)x, // launch 5
                                         (float4*)p_agg, N);

    gemm_l1<<<(N + 127) / 128, 256, SM_TOTAL>>>(           // launch 6 (ncu slot)
        x, (const float*)p_agg, b1, ws2, wn2,
        (float2*)p_s, (float2*)p_t, N);

    finalize_kernel<<<nb, 256>>>(b2, out, N);              // launch 7
}